// round 14
// baseline (speedup 1.0000x reference)
#include <cuda_runtime.h>
#include <cuda_bf16.h>
#include <cstdint>

// ============================================================================
// FourierKARTLayer with HMMA (mma.sync bf16) GEMM2 — 3 launches:
//   K0 prep:  W2 fold -> per-lane B-fragment-ordered bf16 hi/lo arrays
//             (g_WfragH/L) + WcT transpose.
//   K1 angles: theta[tok][q] = X0@WcT + b + w*t  (proven).
//   K2 mma:   grid 128 x 256thr, 16 tokens/block. Per harmonic chunk (K=256:
//             128 sin + 128 cos): build F bf16 hi/lo in smem from register
//             recurrence; 8 warps k-split; mma.sync m16n8k16 3-pass hi/lo
//             split into fp32 C frags; 8-warp reduce; direct V stores.
// ============================================================================

#define D_INF   256
#define NQ      128
#define NK      6
#define NTOK    2048
#define TOKB    8
#define MTOK    16           // tokens per mma block
#define FPITCHB 528          // F smem row pitch bytes (264 bf16)

__device__ float g_WcT[D_INF * NQ];      // [i][q]
__device__ float g_ang[NTOK * NQ];       // [tok][q]
__device__ uint2 g_WfragH[24576];        // B frags, bf16-hi: [c][w][s][nt][lane]
__device__ uint2 g_WfragL[24576];        // B frags, bf16-lo

using u64 = unsigned long long;

__device__ __forceinline__ u64 pack2(float x, float y) {
    u64 r; asm("mov.b64 %0, {%1, %2};" : "=l"(r) : "f"(x), "f"(y)); return r;
}
__device__ __forceinline__ u64 fma2(u64 a, u64 b, u64 c) {
    u64 d; asm("fma.rn.f32x2 %0, %1, %2, %3;" : "=l"(d) : "l"(a), "l"(b), "l"(c)); return d;
}
__device__ __forceinline__ float2 unpack2(u64 a) {
    float2 f; asm("mov.b64 {%0, %1}, %2;" : "=f"(f.x), "=f"(f.y) : "l"(a)); return f;
}
__device__ __forceinline__ u64 add2(u64 a, u64 b) {
    u64 d; asm("add.rn.f32x2 %0, %1, %2;" : "=l"(d) : "l"(a), "l"(b)); return d;
}
__device__ __forceinline__ uint32_t smem_u32(const void* p) {
    return (uint32_t)__cvta_generic_to_shared(p);
}
// pack two floats to bf16x2: low half = lo, high half = hi
__device__ __forceinline__ uint32_t bf16x2(float hi, float lo) {
    uint32_t r;
    asm("cvt.rn.bf16x2.f32 %0, %1, %2;" : "=r"(r) : "f"(hi), "f"(lo));
    return r;
}
__device__ __forceinline__ float bf_lo_f(uint32_t p) { return __uint_as_float(p << 16); }
__device__ __forceinline__ float bf_hi_f(uint32_t p) { return __uint_as_float(p & 0xFFFF0000u); }

#define MMA_BF16(C, a0, a1, a2, a3, b0, b1) \
    asm volatile("mma.sync.aligned.m16n8k16.row.col.f32.bf16.bf16.f32 " \
                 "{%0,%1,%2,%3}, {%4,%5,%6,%7}, {%8,%9}, {%0,%1,%2,%3};" \
                 : "+f"((C)[0]), "+f"((C)[1]), "+f"((C)[2]), "+f"((C)[3]) \
                 : "r"(a0), "r"(a1), "r"(a2), "r"(a3), "r"(b0), "r"(b1))

#define LDMATRIX_X4(r0, r1, r2, r3, addr) \
    asm volatile("ldmatrix.sync.aligned.m8n8.x4.shared.b16 {%0,%1,%2,%3}, [%4];" \
                 : "=r"(r0), "=r"(r1), "=r"(r2), "=r"(r3) : "r"(addr))

// ----------------------------------------------------------------------------
// K0: prep. grid 192 x 256 = 49152 threads.
// Each thread builds ONE b-reg u32 (two consecutive k) for hi and lo arrays.
// Layout linear n = ((((c*8 + w)*2 + s)*8 + nt)*32 + l)*2 + r.
// ----------------------------------------------------------------------------
__global__ void prep_kernel(const float* __restrict__ Wc_w,
                            const float* __restrict__ A,
                            const float* __restrict__ Bp) {
    int n = blockIdx.x * blockDim.x + threadIdx.x;          // 0..49151
    {
        int r  = n & 1;
        int l  = (n >> 1) & 31;
        int nt = (n >> 6) & 7;
        int s  = (n >> 9) & 1;
        int w  = (n >> 10) & 7;
        int c  = n >> 13;                                   // 0..5
        int kc = w * 32 + s * 16 + (l & 3) * 2 + r * 8;     // even, <= 254
        int d  = nt * 8 + (l >> 2);
        int trig = kc >> 7;                                 // 0=sin rows,1=cos
        int q    = kc & 127;

        int base = (d * 128 + q) * NK + c;
        float a0 = __ldg(A + base),     b0 = __ldg(Bp + base);
        float a1 = __ldg(A + base + NK), b1 = __ldg(Bp + base + NK);  // q+1

        float nr0 = rintf(b0 * 0.15915494309189535f);
        float br0 = fmaf(nr0, -6.283185307179586f, b0);
        float nr1 = rintf(b1 * 0.15915494309189535f);
        float br1 = fmaf(nr1, -6.283185307179586f, b1);
        float s0, c0v, s1, c1v;
        __sincosf(br0, &s0, &c0v);
        __sincosf(br1, &s1, &c1v);
        float v0 = trig ? (a0 * s0) : (a0 * c0v);           // W2 value k
        float v1 = trig ? (a1 * s1) : (a1 * c1v);           // W2 value k+1

        uint32_t hi = bf16x2(v1, v0);                       // low half = k
        uint32_t lo = bf16x2(v1 - bf_hi_f(hi), v0 - bf_lo_f(hi));
        ((uint32_t*)g_WfragH)[n] = hi;
        ((uint32_t*)g_WfragL)[n] = lo;
    }
    if (n < D_INF * NQ) {
        int q = n & (NQ - 1);
        int i = n >> 7;
        g_WcT[n] = Wc_w[q * D_INF + i];
    }
}

// ----------------------------------------------------------------------------
// K1: angles. grid 256 x 256 (8 tokens/block). Proven.
// ----------------------------------------------------------------------------
__global__ void __launch_bounds__(256) angles_kernel(
    const float* __restrict__ X0,
    const float* __restrict__ t,
    const float* __restrict__ Wc_b,
    const float* __restrict__ w) {

    __shared__ float Xs[D_INF * TOKB];
    __shared__ u64   E[4 * 2 * NQ];

    const int tid = threadIdx.x;
    const int g0  = blockIdx.x * TOKB;
    const float tb = t[g0 >> 10];

    {
        int tok = tid >> 5;
        int seg = tid & 31;
        const float4* src = (const float4*)(X0 + (size_t)(g0 + tok) * D_INF + seg * 8);
        float4 v0 = src[0];
        float4 v1 = src[1];
        int i0 = seg * 8;
        Xs[(i0 + 0) * TOKB + tok] = v0.x;
        Xs[(i0 + 1) * TOKB + tok] = v0.y;
        Xs[(i0 + 2) * TOKB + tok] = v0.z;
        Xs[(i0 + 3) * TOKB + tok] = v0.w;
        Xs[(i0 + 4) * TOKB + tok] = v1.x;
        Xs[(i0 + 5) * TOKB + tok] = v1.y;
        Xs[(i0 + 6) * TOKB + tok] = v1.z;
        Xs[(i0 + 7) * TOKB + tok] = v1.w;
    }
    __syncthreads();

    {
        const int ih = tid >> 7;
        const int q  = tid & (NQ - 1);
        u64 acc[4] = {0ULL, 0ULL, 0ULL, 0ULL};
        #pragma unroll 8
        for (int s = 0; s < D_INF / 2; s++) {
            int i = ih * (D_INF / 2) + s;
            float wv = __ldg(g_WcT + i * NQ + q);
            u64 wd = pack2(wv, wv);
            ulonglong2 xa = *(const ulonglong2*)(Xs + i * TOKB);
            ulonglong2 xb = *(const ulonglong2*)(Xs + i * TOKB + 4);
            acc[0] = fma2(xa.x, wd, acc[0]);
            acc[1] = fma2(xa.y, wd, acc[1]);
            acc[2] = fma2(xb.x, wd, acc[2]);
            acc[3] = fma2(xb.y, wd, acc[3]);
        }
        #pragma unroll
        for (int p = 0; p < 4; p++)
            E[(p * 2 + ih) * NQ + q] = acc[p];
    }
    __syncthreads();

    {
        const int q  = tid & (NQ - 1);
        const int th = tid >> 7;
        float init = fmaf(w[q], tb, Wc_b[q]);
        u64 bi = pack2(init, init);
        int p0 = th * 2;
        u64 s0 = add2(add2(E[(p0 * 2 + 0) * NQ + q], E[(p0 * 2 + 1) * NQ + q]), bi);
        u64 s1 = add2(add2(E[((p0 + 1) * 2 + 0) * NQ + q], E[((p0 + 1) * 2 + 1) * NQ + q]), bi);
        float2 a01 = unpack2(s0);
        float2 a23 = unpack2(s1);
        float* ap = g_ang + (size_t)(g0 + th * 4) * NQ + q;
        ap[0 * NQ] = a01.x;
        ap[1 * NQ] = a01.y;
        ap[2 * NQ] = a23.x;
        ap[3 * NQ] = a23.y;
    }
}

// ----------------------------------------------------------------------------
// K2: HMMA GEMM2. grid 128 x 256 thr (8 warps), 16 tokens/block.
// smem 32KB: F chunk (Fh@0 8448B, Fl@8448 8448B) then Red [8][16][64] fp32.
// ----------------------------------------------------------------------------
__global__ void __launch_bounds__(256) mma_kernel(float* __restrict__ V) {
    __shared__ __align__(16) char sm[32768];

    const int tid = threadIdx.x;
    const int wid = tid >> 5;
    const int lid = tid & 31;
    const int g0  = blockIdx.x * MTOK;

    // ---- sincos state: thread = (tok = tid>>4, qg = tid&15), 8 q cells ----
    const int tok = tid >> 4;
    const int qg  = tid & 15;
    float s1[8], c1[8], sk[8], ck[8];
    {
        const float* ap = g_ang + (size_t)(g0 + tok) * NQ + qg * 8;
        #pragma unroll
        for (int j = 0; j < 8; j++) {
            float a = ap[j];
            float nr = rintf(a * 0.15915494309189535f);
            float ar = fmaf(nr, -6.283185307179586f, a);
            __sincosf(ar, &s1[j], &c1[j]);
            sk[j] = s1[j];
            ck[j] = c1[j];
        }
    }

    float C[8][4];
    #pragma unroll
    for (int nt = 0; nt < 8; nt++)
        #pragma unroll
        for (int r = 0; r < 4; r++) C[nt][r] = 0.f;

    const uint32_t fh_base = smem_u32(sm);
    const uint32_t fl_base = fh_base + 8448;
    // F emit offsets: row tok (pitch 528B), sin col q, cos col 128+q
    char* fhp = sm + tok * FPITCHB + qg * 16;          // qg*8 cols * 2B
    char* flp = fhp + 8448;
    // ldmatrix per-lane address pieces: row = lid&15, kcol += (lid>>4)*8
    const uint32_t lrow_off = (uint32_t)(lid & 15) * FPITCHB + (uint32_t)(lid >> 4) * 16;

    for (int c = 0; c < NK; c++) {
        // ---- emit F chunk (harmonic c+1) --------------------------------
        #pragma unroll
        for (int jp = 0; jp < 4; jp++) {
            uint32_t sh = bf16x2(sk[2 * jp + 1], sk[2 * jp]);
            uint32_t sl = bf16x2(sk[2 * jp + 1] - bf_hi_f(sh), sk[2 * jp] - bf_lo_f(sh));
            uint32_t chv = bf16x2(ck[2 * jp + 1], ck[2 * jp]);
            uint32_t cl = bf16x2(ck[2 * jp + 1] - bf_hi_f(chv), ck[2 * jp] - bf_lo_f(chv));
            *(uint32_t*)(fhp + jp * 4)       = sh;     // sin cols
            *(uint32_t*)(flp + jp * 4)       = sl;
            *(uint32_t*)(fhp + 256 + jp * 4) = chv;    // cos cols (+128*2B)
            *(uint32_t*)(flp + 256 + jp * 4) = cl;
        }
        __syncthreads();

        // ---- mma: warp k-window = wid*32, 2 ksteps of 16 ----------------
        #pragma unroll
        for (int s = 0; s < 2; s++) {
            int k0 = wid * 32 + s * 16;
            uint32_t ah0, ah1, ah2, ah3, al0, al1, al2, al3;
            LDMATRIX_X4(ah0, ah1, ah2, ah3, fh_base + lrow_off + (uint32_t)k0 * 2);
            LDMATRIX_X4(al0, al1, al2, al3, fl_base + lrow_off + (uint32_t)k0 * 2);

            int idx2 = (((c * 8 + wid) * 2 + s) * 8) * 32 + lid;
            #pragma unroll
            for (int nt = 0; nt < 8; nt++, idx2 += 32) {
                uint2 wh = __ldg(g_WfragH + idx2);
                uint2 wl = __ldg(g_WfragL + idx2);
                MMA_BF16(C[nt], ah0, ah1, ah2, ah3, wh.x, wh.y);
                MMA_BF16(C[nt], al0, al1, al2, al3, wh.x, wh.y);
                MMA_BF16(C[nt], ah0, ah1, ah2, ah3, wl.x, wl.y);
            }
        }
        __syncthreads();

        // ---- advance harmonic recurrence --------------------------------
        #pragma unroll
        for (int j = 0; j < 8; j++) {
            float ns = fmaf(sk[j], c1[j], ck[j] * s1[j]);
            float nc = fmaf(ck[j], c1[j], -sk[j] * s1[j]);
            sk[j] = ns; ck[j] = nc;
        }
    }

    // ---- reduction over 8 k-split warps ---------------------------------
    float* Red = (float*)sm;                 // [8][16 tok][64 d]
    {
        int row  = lid >> 2;
        int col0 = (lid & 3) * 2;
        #pragma unroll
        for (int nt = 0; nt < 8; nt++) {
            int col = nt * 8 + col0;
            *(float2*)&Red[(wid * 16 + row) * 64 + col]     = make_float2(C[nt][0], C[nt][1]);
            *(float2*)&Red[(wid * 16 + row + 8) * 64 + col] = make_float2(C[nt][2], C[nt][3]);
        }
    }
    __syncthreads();

    {
        int otok = tid >> 4;
        int d0   = (tid & 15) * 4;
        float4 s = make_float4(0.f, 0.f, 0.f, 0.f);
        #pragma unroll
        for (int w8 = 0; w8 < 8; w8++) {
            float4 r = *(const float4*)&Red[(w8 * 16 + otok) * 64 + d0];
            s.x += r.x; s.y += r.y; s.z += r.z; s.w += r.w;
        }
        *(float4*)&V[(size_t)(g0 + otok) * 64 + d0] = s;
    }
}

// ----------------------------------------------------------------------------
extern "C" void kernel_launch(void* const* d_in, const int* in_sizes, int n_in,
                              void* d_out, int out_size) {
    const float* X0   = (const float*)d_in[0];
    const float* t    = (const float*)d_in[1];
    const float* Wc_w = (const float*)d_in[2];
    const float* Wc_b = (const float*)d_in[3];
    const float* w    = (const float*)d_in[4];
    const float* A    = (const float*)d_in[5];
    const float* Bp   = (const float*)d_in[6];
    float* V = (float*)d_out;

    prep_kernel<<<192, 256>>>(Wc_w, A, Bp);
    angles_kernel<<<NTOK / TOKB, 256>>>(X0, t, Wc_b, w);
    mma_kernel<<<NTOK / MTOK, 256>>>(V);
}

// round 15
// speedup vs baseline: 1.0732x; 1.0732x over previous
#include <cuda_runtime.h>
#include <cuda_bf16.h>
#include <cstdint>

// ============================================================================
// FourierKARTLayer with HMMA (mma.sync bf16) GEMM2 — 2 launches:
//   K1 fused: blocks 0-255   -> angles theta[tok][q] = X0@WcT + b + w*t
//             blocks 256-447 -> W2 fold into per-lane B-frag bf16 hi/lo arrays
//   K2 mma:   grid 256 = 128 token-tiles(16) x 2 d-halves, 256 thr (8 warps).
//             Per harmonic chunk: F bf16 hi/lo from register recurrence ->
//             smem; 8-warp k-split; m16n8k16 3-pass hi/lo split; fp32 C frags;
//             8-warp reduce; disjoint V stores.
// ============================================================================

#define D_INF   256
#define NQ      128
#define NK      6
#define NTOK    2048
#define TOKB    8
#define MTOK    16           // tokens per mma tile
#define FPITCHB 528          // F smem row pitch bytes (264 bf16)

__device__ float g_WcT[D_INF * NQ];      // [i][q]
__device__ float g_ang[NTOK * NQ];       // [tok][q]
__device__ uint2 g_WfragH[24576];        // B frags, bf16-hi: [c][w][s][nt][lane]
__device__ uint2 g_WfragL[24576];        // B frags, bf16-lo

using u64 = unsigned long long;

__device__ __forceinline__ u64 pack2(float x, float y) {
    u64 r; asm("mov.b64 %0, {%1, %2};" : "=l"(r) : "f"(x), "f"(y)); return r;
}
__device__ __forceinline__ u64 fma2(u64 a, u64 b, u64 c) {
    u64 d; asm("fma.rn.f32x2 %0, %1, %2, %3;" : "=l"(d) : "l"(a), "l"(b), "l"(c)); return d;
}
__device__ __forceinline__ float2 unpack2(u64 a) {
    float2 f; asm("mov.b64 {%0, %1}, %2;" : "=f"(f.x), "=f"(f.y) : "l"(a)); return f;
}
__device__ __forceinline__ u64 add2(u64 a, u64 b) {
    u64 d; asm("add.rn.f32x2 %0, %1, %2;" : "=l"(d) : "l"(a), "l"(b)); return d;
}
__device__ __forceinline__ uint32_t smem_u32(const void* p) {
    return (uint32_t)__cvta_generic_to_shared(p);
}
__device__ __forceinline__ uint32_t bf16x2(float hi, float lo) {
    uint32_t r;
    asm("cvt.rn.bf16x2.f32 %0, %1, %2;" : "=r"(r) : "f"(hi), "f"(lo));
    return r;
}
__device__ __forceinline__ float bf_lo_f(uint32_t p) { return __uint_as_float(p << 16); }
__device__ __forceinline__ float bf_hi_f(uint32_t p) { return __uint_as_float(p & 0xFFFF0000u); }

#define MMA_BF16(C, a0, a1, a2, a3, b0, b1) \
    asm volatile("mma.sync.aligned.m16n8k16.row.col.f32.bf16.bf16.f32 " \
                 "{%0,%1,%2,%3}, {%4,%5,%6,%7}, {%8,%9}, {%0,%1,%2,%3};" \
                 : "+f"((C)[0]), "+f"((C)[1]), "+f"((C)[2]), "+f"((C)[3]) \
                 : "r"(a0), "r"(a1), "r"(a2), "r"(a3), "r"(b0), "r"(b1))

#define LDMATRIX_X4(r0, r1, r2, r3, addr) \
    asm volatile("ldmatrix.sync.aligned.m8n8.x4.shared.b16 {%0,%1,%2,%3}, [%4];" \
                 : "=r"(r0), "=r"(r1), "=r"(r2), "=r"(r3) : "r"(addr))

// ----------------------------------------------------------------------------
// K1 fused: angles (blocks 0-255) + W2 frag fold (blocks 256-447).
// ----------------------------------------------------------------------------
__global__ void __launch_bounds__(256) k1_kernel(
    const float* __restrict__ X0,
    const float* __restrict__ t,
    const float* __restrict__ Wc_w,
    const float* __restrict__ Wc_b,
    const float* __restrict__ w,
    const float* __restrict__ A,
    const float* __restrict__ Bp) {

    const int tid = threadIdx.x;

    if (blockIdx.x >= 256) {
        // ---- W2 frag fold --------------------------------------------------
        int n = (blockIdx.x - 256) * 256 + tid;             // 0..49151
        {
            int r  = n & 1;
            int l  = (n >> 1) & 31;
            int nt = (n >> 6) & 7;
            int s  = (n >> 9) & 1;
            int wq = (n >> 10) & 7;
            int c  = n >> 13;                               // 0..5
            int kc = wq * 32 + s * 16 + (l & 3) * 2 + r * 8;
            int d  = nt * 8 + (l >> 2);
            int trig = kc >> 7;                             // 0=sin rows, 1=cos
            int q    = kc & 127;

            int base = (d * 128 + q) * NK + c;
            float a0 = __ldg(A + base),      b0 = __ldg(Bp + base);
            float a1 = __ldg(A + base + NK), b1 = __ldg(Bp + base + NK);

            float nr0 = rintf(b0 * 0.15915494309189535f);
            float br0 = fmaf(nr0, -6.283185307179586f, b0);
            float nr1 = rintf(b1 * 0.15915494309189535f);
            float br1 = fmaf(nr1, -6.283185307179586f, b1);
            float s0, c0v, s1, c1v;
            __sincosf(br0, &s0, &c0v);
            __sincosf(br1, &s1, &c1v);
            float v0 = trig ? (a0 * s0) : (a0 * c0v);
            float v1 = trig ? (a1 * s1) : (a1 * c1v);

            uint32_t hi = bf16x2(v1, v0);
            uint32_t lo = bf16x2(v1 - bf_hi_f(hi), v0 - bf_lo_f(hi));
            ((uint32_t*)g_WfragH)[n] = hi;
            ((uint32_t*)g_WfragL)[n] = lo;
        }
        if (n < D_INF * NQ) {
            int q = n & (NQ - 1);
            int i = n >> 7;
            g_WcT[n] = Wc_w[q * D_INF + i];
        }
        return;
    }

    // ---- angles block ------------------------------------------------------
    __shared__ float Xs[D_INF * TOKB];
    __shared__ u64   E[4 * 2 * NQ];

    const int g0  = blockIdx.x * TOKB;
    const float tb = t[g0 >> 10];

    {
        int tok = tid >> 5;
        int seg = tid & 31;
        const float4* src = (const float4*)(X0 + (size_t)(g0 + tok) * D_INF + seg * 8);
        float4 v0 = src[0];
        float4 v1 = src[1];
        int i0 = seg * 8;
        Xs[(i0 + 0) * TOKB + tok] = v0.x;
        Xs[(i0 + 1) * TOKB + tok] = v0.y;
        Xs[(i0 + 2) * TOKB + tok] = v0.z;
        Xs[(i0 + 3) * TOKB + tok] = v0.w;
        Xs[(i0 + 4) * TOKB + tok] = v1.x;
        Xs[(i0 + 5) * TOKB + tok] = v1.y;
        Xs[(i0 + 6) * TOKB + tok] = v1.z;
        Xs[(i0 + 7) * TOKB + tok] = v1.w;
    }
    __syncthreads();

    {
        const int ih = tid >> 7;
        const int q  = tid & (NQ - 1);
        u64 acc[4] = {0ULL, 0ULL, 0ULL, 0ULL};
        #pragma unroll 8
        for (int s = 0; s < D_INF / 2; s++) {
            int i = ih * (D_INF / 2) + s;
            float wv = __ldg(g_WcT + i * NQ + q);
            u64 wd = pack2(wv, wv);
            ulonglong2 xa = *(const ulonglong2*)(Xs + i * TOKB);
            ulonglong2 xb = *(const ulonglong2*)(Xs + i * TOKB + 4);
            acc[0] = fma2(xa.x, wd, acc[0]);
            acc[1] = fma2(xa.y, wd, acc[1]);
            acc[2] = fma2(xb.x, wd, acc[2]);
            acc[3] = fma2(xb.y, wd, acc[3]);
        }
        #pragma unroll
        for (int p = 0; p < 4; p++)
            E[(p * 2 + ih) * NQ + q] = acc[p];
    }
    __syncthreads();

    {
        const int q  = tid & (NQ - 1);
        const int th = tid >> 7;
        float init = fmaf(w[q], tb, Wc_b[q]);
        u64 bi = pack2(init, init);
        int p0 = th * 2;
        u64 s0 = add2(add2(E[(p0 * 2 + 0) * NQ + q], E[(p0 * 2 + 1) * NQ + q]), bi);
        u64 s1 = add2(add2(E[((p0 + 1) * 2 + 0) * NQ + q], E[((p0 + 1) * 2 + 1) * NQ + q]), bi);
        float2 a01 = unpack2(s0);
        float2 a23 = unpack2(s1);
        float* ap = g_ang + (size_t)(g0 + th * 4) * NQ + q;
        ap[0 * NQ] = a01.x;
        ap[1 * NQ] = a01.y;
        ap[2 * NQ] = a23.x;
        ap[3 * NQ] = a23.y;
    }
}

// NOTE: k1 angles blocks read g_WcT written by prep blocks of the SAME launch?
// NO — angles uses g_WcT too. Avoid the race: angles reads Wc_w directly via
// a per-block staging identical to R7? Simpler: angles blocks here read
// g_WcT... To keep it safe, angles reads Wc_w DIRECTLY (strided __ldg) is
// slow. Instead: prep blocks write g_WcT, but angles blocks DON'T use it —
// they load Wc_w rows via the same transposed access used in prep of R1-R9
// pre-kernels. To preserve the proven angles code (which consumes g_WcT),
// we keep a separate tiny transpose INSIDE each angles block: cheap (one
// 32KB read per block, served from L2). Implemented above?  -- NO.
// Resolution implemented below: angles uses Wc_w directly with q-major
// access: wv = Wc_w[q * D_INF + i] (uncoalesced per-warp but L2-cached,
// 128B line per q row reused 256x across i). See angles loop: it uses
// g_WcT... fixed in k1b below.

// ----------------------------------------------------------------------------
// K2: HMMA GEMM2. grid 256 = 128 tiles x 2 d-halves, 256 thr (8 warps).
// smem 32KB static: F chunk (Fh@0 8448B, Fl@8448) ; Red [8][16][32] aliases.
// ----------------------------------------------------------------------------
__global__ void __launch_bounds__(256) mma_kernel(float* __restrict__ V) {
    __shared__ __align__(16) char sm[32768];

    const int tid = threadIdx.x;
    const int wid = tid >> 5;
    const int lid = tid & 31;
    const int tile = blockIdx.x >> 1;
    const int h    = blockIdx.x & 1;         // d-half
    const int g0   = tile * MTOK;

    // ---- sincos state: thread = (tok = tid>>4, qg = tid&15), 8 q cells ----
    const int tok = tid >> 4;
    const int qg  = tid & 15;
    float s1[8], c1[8], sk[8], ck[8];
    {
        const float* ap = g_ang + (size_t)(g0 + tok) * NQ + qg * 8;
        #pragma unroll
        for (int j = 0; j < 8; j++) {
            float a = ap[j];
            float nr = rintf(a * 0.15915494309189535f);
            float ar = fmaf(nr, -6.283185307179586f, a);
            __sincosf(ar, &s1[j], &c1[j]);
            sk[j] = s1[j];
            ck[j] = c1[j];
        }
    }

    float C[4][4];
    #pragma unroll
    for (int nt = 0; nt < 4; nt++)
        #pragma unroll
        for (int r = 0; r < 4; r++) C[nt][r] = 0.f;

    const uint32_t fh_base = smem_u32(sm);
    const uint32_t fl_base = fh_base + 8448;
    char* fhp = sm + tok * FPITCHB + qg * 16;
    char* flp = fhp + 8448;
    const uint32_t lrow_off = (uint32_t)(lid & 15) * FPITCHB + (uint32_t)(lid >> 4) * 16;

    for (int c = 0; c < NK; c++) {
        // ---- emit F chunk (harmonic c+1) --------------------------------
        #pragma unroll
        for (int jp = 0; jp < 4; jp++) {
            uint32_t sh  = bf16x2(sk[2 * jp + 1], sk[2 * jp]);
            uint32_t sl  = bf16x2(sk[2 * jp + 1] - bf_hi_f(sh), sk[2 * jp] - bf_lo_f(sh));
            uint32_t chv = bf16x2(ck[2 * jp + 1], ck[2 * jp]);
            uint32_t cl  = bf16x2(ck[2 * jp + 1] - bf_hi_f(chv), ck[2 * jp] - bf_lo_f(chv));
            *(uint32_t*)(fhp + jp * 4)       = sh;
            *(uint32_t*)(flp + jp * 4)       = sl;
            *(uint32_t*)(fhp + 256 + jp * 4) = chv;
            *(uint32_t*)(flp + 256 + jp * 4) = cl;
        }
        __syncthreads();

        // ---- mma: warp k-window = wid*32, 2 ksteps of 16 ----------------
        #pragma unroll
        for (int s = 0; s < 2; s++) {
            int k0 = wid * 32 + s * 16;
            uint32_t ah0, ah1, ah2, ah3, al0, al1, al2, al3;
            LDMATRIX_X4(ah0, ah1, ah2, ah3, fh_base + lrow_off + (uint32_t)k0 * 2);
            LDMATRIX_X4(al0, al1, al2, al3, fl_base + lrow_off + (uint32_t)k0 * 2);

            int idx2 = ((((c * 8 + wid) * 2 + s) * 8) + h * 4) * 32 + lid;
            #pragma unroll
            for (int nt = 0; nt < 4; nt++, idx2 += 32) {
                uint2 wh = __ldg(g_WfragH + idx2);
                uint2 wl = __ldg(g_WfragL + idx2);
                MMA_BF16(C[nt], ah0, ah1, ah2, ah3, wh.x, wh.y);
                MMA_BF16(C[nt], al0, al1, al2, al3, wh.x, wh.y);
                MMA_BF16(C[nt], ah0, ah1, ah2, ah3, wl.x, wl.y);
            }
        }
        __syncthreads();

        // ---- advance harmonic recurrence --------------------------------
        #pragma unroll
        for (int j = 0; j < 8; j++) {
            float ns = fmaf(sk[j], c1[j], ck[j] * s1[j]);
            float nc = fmaf(ck[j], c1[j], -sk[j] * s1[j]);
            sk[j] = ns; ck[j] = nc;
        }
    }

    // ---- reduction over 8 k-split warps (32 d cols) ---------------------
    float* Red = (float*)sm;                 // [8][16 tok][32 d]
    {
        int row  = lid >> 2;
        int col0 = (lid & 3) * 2;
        #pragma unroll
        for (int nt = 0; nt < 4; nt++) {
            int col = nt * 8 + col0;
            *(float2*)&Red[(wid * 16 + row) * 32 + col]     = make_float2(C[nt][0], C[nt][1]);
            *(float2*)&Red[(wid * 16 + row + 8) * 32 + col] = make_float2(C[nt][2], C[nt][3]);
        }
    }
    __syncthreads();

    {
        int otok = tid >> 4;                 // 0..15
        int d0   = (tid & 15) * 2;           // 0..30
        float2 s = make_float2(0.f, 0.f);
        #pragma unroll
        for (int w8 = 0; w8 < 8; w8++) {
            float2 r = *(const float2*)&Red[(w8 * 16 + otok) * 32 + d0];
            s.x += r.x; s.y += r.y;
        }
        *(float2*)&V[(size_t)(g0 + otok) * 64 + h * 32 + d0] = s;
    }
}

// ----------------------------------------------------------------------------
extern "C" void kernel_launch(void* const* d_in, const int* in_sizes, int n_in,
                              void* d_out, int out_size) {
    const float* X0   = (const float*)d_in[0];
    const float* t    = (const float*)d_in[1];
    const float* Wc_w = (const float*)d_in[2];
    const float* Wc_b = (const float*)d_in[3];
    const float* w    = (const float*)d_in[4];
    const float* A    = (const float*)d_in[5];
    const float* Bp   = (const float*)d_in[6];
    float* V = (float*)d_out;

    // g_WcT is consumed by angles blocks of the SAME fused launch as the prep
    // blocks that write it -> RACE. Resolve by writing WcT in a tiny separate
    // kernel launched FIRST (32 blocks, ~launch-overhead cost only; runs
    // while k1's angle blocks are still being scheduled... must complete
    // before k1 starts: stream-ordered, so correctness holds).
    extern __global__ void wct_kernel(const float*);
    wct_kernel<<<128, 256>>>(Wc_w);
    k1_kernel<<<448, 256>>>(X0, t, Wc_w, Wc_b, w, A, Bp);
    mma_kernel<<<256, 256>>>(V);
}

// Tiny WcT transpose kernel (32768 elems / 32768 threads).
__global__ void wct_kernel(const float* __restrict__ Wc_w) {
    int n = blockIdx.x * blockDim.x + threadIdx.x;      // 0..32767
    int q = n & (NQ - 1);
    int i = n >> 7;
    g_WcT[n] = Wc_w[q * D_INF + i];
}